// round 10
// baseline (speedup 1.0000x reference)
#include <cuda_runtime.h>
#include <cuda_fp16.h>

#define B 8
#define N 2048
#define F 64
#define MAXNNZ 256
#define BN (B*N)  // 16384
#define LRELU_SLOPE 0.2f

// ---- scratch (static device arrays; re-initialized every launch) ----
__device__ float  g_h[BN*F];                       // 4 MB fp32 h (cvec path)
__device__ __half g_hh[BN*F];                      // 2 MB fp16 h (k_out gather path)
__device__ float  g_f1[BN];
__device__ float  g_f2[BN];
__device__ float  g_Dsum[BN];                      // sum of expm1 terms per column
__device__ float  g_invD[BN];
__device__ float  g_c[B*F];                        // per-batch constant row
__device__ int    g_nnz[BN];
__device__ float2 g_pairs[(size_t)BN*MAXNNZ];      // (j as int bits, p), zero-padded to %8

// ---------------- A: h = input@W (fp32 + fp16), f1/f2, zero accumulators ----------------
__global__ void k_hproj(const float* __restrict__ in, const float* __restrict__ W,
                        const float* __restrict__ a1, const float* __restrict__ a2) {
    __shared__ float Ws[F*F];
    __shared__ float a1s[F], a2s[F];
    __shared__ float ins[8*F];
    __shared__ float hs[8*F];
    int tid = threadIdx.x;
    int rowBase = blockIdx.x * 8;

    if (blockIdx.x < 32) g_Dsum[blockIdx.x * 512 + tid] = 0.f;
    if (blockIdx.x == 32 && tid < B*F) g_c[tid] = 0.f;

    for (int t = tid; t < F*F; t += 512) Ws[t] = W[t];
    if (tid < F) { a1s[tid] = a1[tid]; a2s[tid] = a2[tid]; }
    ins[tid] = in[rowBase*F + tid];
    __syncthreads();

    int r = tid >> 6, o = tid & 63;
    float acc = 0.f;
#pragma unroll
    for (int f = 0; f < F; f++) acc += ins[r*F + f] * Ws[f*F + o];
    g_h[(rowBase + r)*F + o]  = acc;
    g_hh[(rowBase + r)*F + o] = __float2half(acc);
    hs[tid] = acc;
    __syncthreads();

    int w = tid >> 5, lane = tid & 31;
    if (w < 8) {
        float v1 = hs[w*F + lane]*a1s[lane] + hs[w*F + lane + 32]*a1s[lane + 32];
        float v2 = hs[w*F + lane]*a2s[lane] + hs[w*F + lane + 32]*a2s[lane + 32];
#pragma unroll
        for (int off = 16; off; off >>= 1) {
            v1 += __shfl_down_sync(0xffffffffu, v1, off);
            v2 += __shfl_down_sync(0xffffffffu, v2, off);
        }
        if (lane == 0) { g_f1[rowBase + w] = v1; g_f2[rowBase + w] = v2; }
    }
}

// ---------------- B: stream adj 8 elems/lane/iter; direct-REDG Dsum ----------------
// block = 512 threads = 16 warps = 16 rows; two coalesced LDG.128 groups per iter.
__global__ void k_scan(const float* __restrict__ adj) {
    __shared__ float4 f2s4[N/4];      // 8 KB
    int tid = threadIdx.x;
    int b  = blockIdx.x >> 7;
    int i0 = (blockIdx.x & 127) * 16;

    float* f2s = (float*)f2s4;
    for (int t = tid; t < N; t += 512) f2s[t] = g_f2[b*N + t];
    __syncthreads();

    int w = tid >> 5, lane = tid & 31;
    int row = b*N + i0 + w;
    float f1i = g_f1[row];
    const float4* __restrict__ arow = (const float4*)(adj + (size_t)row * N);
    float2* pbase = g_pairs + (size_t)row * MAXNNZ;
    float*  Drow  = g_Dsum + b*N;
    unsigned lmask = (1u << lane) - 1u;
    int nnz = 0;

    float4 a0 = arow[lane], a1 = arow[lane + 32];
#pragma unroll 1
    for (int it = 0; it < 8; it++) {
        float4 n0, n1;
        if (it < 7) { n0 = arow[(it+1)*64 + lane]; n1 = arow[(it+1)*64 + lane + 32]; }
        int t0 = it*64 + lane, t1 = t0 + 32;

        unsigned msk =
            (a0.x != 0.f ?   1u : 0u) | (a0.y != 0.f ?   2u : 0u) |
            (a0.z != 0.f ?   4u : 0u) | (a0.w != 0.f ?   8u : 0u) |
            (a1.x != 0.f ?  16u : 0u) | (a1.y != 0.f ?  32u : 0u) |
            (a1.z != 0.f ?  64u : 0u) | (a1.w != 0.f ? 128u : 0u);
        int c = __popc(msk);

        unsigned m0 = __ballot_sync(0xffffffffu, c & 1);
        unsigned m1 = __ballot_sync(0xffffffffu, c & 2);
        unsigned m2 = __ballot_sync(0xffffffffu, c & 4);
        unsigned m3 = __ballot_sync(0xffffffffu, c & 8);
        int base = nnz + __popc(m0 & lmask) + 2*__popc(m1 & lmask)
                 + 4*__popc(m2 & lmask) + 8*__popc(m3 & lmask);
        nnz += __popc(m0) + 2*__popc(m1) + 4*__popc(m2) + 8*__popc(m3);

        if (msk) {
            float4 f2v0, f2v1;
            if (msk & 0x0Fu) f2v0 = f2s4[t0];
            if (msk & 0xF0u) f2v1 = f2s4[t1];
            do {
                int k = __ffs(msk) - 1;
                msk &= msk - 1;
                float fv;
                int j;
                if (k < 4) {
                    fv = (k & 1) ? ((k & 2) ? f2v0.w : f2v0.y)
                                 : ((k & 2) ? f2v0.z : f2v0.x);
                    j = 4*t0 + k;
                } else {
                    int kk = k - 4;
                    fv = (kk & 1) ? ((kk & 2) ? f2v1.w : f2v1.y)
                                  : ((kk & 2) ? f2v1.z : f2v1.x);
                    j = 4*t1 + kk;
                }
                float e = f1i + fv;
                e = (e >= 0.f) ? e : LRELU_SLOPE * e;
                float p = __expf(e) - 1.f;
                if (base < MAXNNZ)
                    pbase[base] = make_float2(__int_as_float(j), p);
                base++;
                atomicAdd(&Drow[j], p);               // direct spread REDG
            } while (msk);
        }
        a0 = n0; a1 = n1;
    }
    nnz = min(nnz, MAXNNZ);
    if (lane == 0) g_nnz[row] = nnz;
    int npad = (nnz + 7) & ~7;
    if (nnz + lane < npad) pbase[nnz + lane] = make_float2(0.f, 0.f);
}

// ---------------- C: invD = 1/(N+Dsum); c[b,o] += sum_j invD[j]*h[j,o] ----------------
__global__ void k_cvec() {
    __shared__ float inv_s[64];
    __shared__ float part[512];
    int tid = threadIdx.x;
    int b  = blockIdx.x >> 5;
    int j0 = (blockIdx.x & 31) * 64;

    if (tid < 64) {
        float v = 1.f / ((float)N + g_Dsum[b*N + j0 + tid]);
        g_invD[b*N + j0 + tid] = v;
        inv_s[tid] = v;
    }
    __syncthreads();

    int r = tid >> 6, o = tid & 63;
    float acc = 0.f;
#pragma unroll
    for (int q = 0; q < 8; q++) {
        int jj = q*8 + r;
        acc += inv_s[jj] * g_h[(size_t)(b*N + j0 + jj)*F + o];
    }
    part[tid] = acc;
    __syncthreads();
    if (tid < 64) {
        float s = 0.f;
#pragma unroll
        for (int q = 0; q < 8; q++) s += part[q*64 + tid];
        atomicAdd(&g_c[b*F + tid], s);
    }
}

// ---------------- D: sparse fp16 gather, half-warp scheme (R9 proven) ----------------
__global__ void k_out(const float* __restrict__ in, const float* __restrict__ bias,
                      float* __restrict__ out) {
    __shared__ float  inv_s[N];                    // 8 KB
    __shared__ float2 pairs_s[16 * MAXNNZ];        // 32 KB (j*16 as int bits, w)
    int tid = threadIdx.x;
    int w = tid >> 5, lane = tid & 31;
    int half = lane >> 4, fl = lane & 15;
    int rowBase = blockIdx.x * 16;
    int b = rowBase >> 11;

    ((float4*)inv_s)[tid] = ((const float4*)(g_invD + b*N))[tid];
    __syncthreads();

    int row = rowBase + w;
    int i = row & (N - 1);
    int npad = (g_nnz[row] + 7) & ~7;
    {
        const float2* __restrict__ pbase = g_pairs + (size_t)row * MAXNNZ;
        float2* ps2 = pairs_s + w * MAXNNZ;
        for (int t = lane; t < npad; t += 32) {
            float2 pr = pbase[t];
            int j = __float_as_int(pr.x);
            ps2[t] = make_float2(__int_as_float(j * 16), pr.y * inv_s[j]);
        }
    }
    __syncwarp();

    const float2* __restrict__ ps2 = pairs_s + w * MAXNNZ;
    const uint2* __restrict__ hh = (const uint2*)(g_hh + (size_t)b*N*F);

    float ax = 0.f, ay = 0.f, az = 0.f, aw = 0.f;
#pragma unroll 1
    for (int k0 = 0; k0 < npad; k0 += 8) {
#pragma unroll
        for (int u = 0; u < 4; u++) {
            float2 pr = ps2[k0 + 2*u + half];
            int j16 = __float_as_int(pr.x);
            uint2 hv = hh[j16 + fl];
            float2 f01 = __half22float2(*(const __half2*)&hv.x);
            float2 f23 = __half22float2(*(const __half2*)&hv.y);
            ax += pr.y * f01.x;
            ay += pr.y * f01.y;
            az += pr.y * f23.x;
            aw += pr.y * f23.y;
        }
    }

    ax += __shfl_xor_sync(0xffffffffu, ax, 16);
    ay += __shfl_xor_sync(0xffffffffu, ay, 16);
    az += __shfl_xor_sync(0xffffffffu, az, 16);
    aw += __shfl_xor_sync(0xffffffffu, aw, 16);

    if (half == 0) {
        int off = row * F + fl * 4;
        float4 cv = ((const float4*)(g_c + b*F))[fl];
        float4 bv = ((const float4*)(bias + i*F))[fl];
        float4 iv = *(const float4*)(in + off);
        float v0 = ax + cv.x + bv.x + iv.x;
        float v1 = ay + cv.y + bv.y + iv.y;
        float v2 = az + cv.z + bv.z + iv.z;
        float v3 = aw + cv.w + bv.w + iv.w;
        float4 res;
        res.x = (v0 > 0.f) ? v0 : expm1f(v0);
        res.y = (v1 > 0.f) ? v1 : expm1f(v1);
        res.z = (v2 > 0.f) ? v2 : expm1f(v2);
        res.w = (v3 > 0.f) ? v3 : expm1f(v3);
        *(float4*)(out + off) = res;
    }
}

// ---------------- launch ----------------
extern "C" void kernel_launch(void* const* d_in, const int* in_sizes, int n_in,
                              void* d_out, int out_size) {
    const float* input = (const float*)d_in[0];
    const float* adj   = (const float*)d_in[1];
    const float* W     = (const float*)d_in[2];
    const float* a1    = (const float*)d_in[3];
    const float* a2    = (const float*)d_in[4];
    const float* bias  = (const float*)d_in[5];
    float* out = (float*)d_out;

    k_hproj<<<BN/8,  512>>>(input, W, a1, a2);
    k_scan <<<BN/16, 512>>>(adj);
    k_cvec <<<B*32,  512>>>();
    k_out  <<<BN/16, 512>>>(input, bias, out);
}

// round 11
// speedup vs baseline: 1.0208x; 1.0208x over previous
#include <cuda_runtime.h>
#include <cuda_fp16.h>

#define B 8
#define N 2048
#define F 64
#define MAXNNZ 256
#define BN (B*N)  // 16384
#define LRELU_SLOPE 0.2f

// ---- scratch (static device arrays; re-initialized every launch) ----
__device__ float  g_h[BN*F];                       // 4 MB fp32 h (cvec path)
__device__ __half g_hh[BN*F];                      // 2 MB fp16 h (k_out gather path)
__device__ float  g_f1[BN];
__device__ float  g_f2[BN];
__device__ float  g_Dsum[BN];                      // sum of expm1 terms per column
__device__ float  g_invD[BN];
__device__ float  g_c[B*F];                        // per-batch constant row
__device__ int    g_nnz[BN];
__device__ float2 g_pairs[(size_t)BN*MAXNNZ];      // (j as int bits, p), zero-padded to %8

// ---------------- A: h = input@W (fp32 + fp16), f1/f2, zero accumulators ----------------
__global__ void k_hproj(const float* __restrict__ in, const float* __restrict__ W,
                        const float* __restrict__ a1, const float* __restrict__ a2) {
    __shared__ float Ws[F*F];
    __shared__ float a1s[F], a2s[F];
    __shared__ float ins[8*F];
    __shared__ float hs[8*F];
    int tid = threadIdx.x;
    int rowBase = blockIdx.x * 8;

    if (blockIdx.x < 32) g_Dsum[blockIdx.x * 512 + tid] = 0.f;
    if (blockIdx.x == 32 && tid < B*F) g_c[tid] = 0.f;

    for (int t = tid; t < F*F; t += 512) Ws[t] = W[t];
    if (tid < F) { a1s[tid] = a1[tid]; a2s[tid] = a2[tid]; }
    ins[tid] = in[rowBase*F + tid];
    __syncthreads();

    int r = tid >> 6, o = tid & 63;
    float acc = 0.f;
#pragma unroll
    for (int f = 0; f < F; f++) acc += ins[r*F + f] * Ws[f*F + o];
    g_h[(rowBase + r)*F + o]  = acc;
    g_hh[(rowBase + r)*F + o] = __float2half(acc);
    hs[tid] = acc;
    __syncthreads();

    int w = tid >> 5, lane = tid & 31;
    if (w < 8) {
        float v1 = hs[w*F + lane]*a1s[lane] + hs[w*F + lane + 32]*a1s[lane + 32];
        float v2 = hs[w*F + lane]*a2s[lane] + hs[w*F + lane + 32]*a2s[lane + 32];
#pragma unroll
        for (int off = 16; off; off >>= 1) {
            v1 += __shfl_down_sync(0xffffffffu, v1, off);
            v2 += __shfl_down_sync(0xffffffffu, v2, off);
        }
        if (lane == 0) { g_f1[rowBase + w] = v1; g_f2[rowBase + w] = v2; }
    }
}

// ---------------- B: stream adj; R9 ballot/drain structure; 32 rows/block ----------
// block = 1024 threads = 32 warps = 32 rows; 2-deep adj prefetch; Dpart smem + flush.
__global__ void k_scan(const float* __restrict__ adj) {
    __shared__ float  Dpart[N];       // 8 KB
    __shared__ float4 f2s4[N/4];      // 8 KB
    int tid = threadIdx.x;
    int b  = blockIdx.x >> 6;         // 64 blocks per batch
    int i0 = (blockIdx.x & 63) * 32;

    for (int t = tid; t < N; t += 1024) Dpart[t] = 0.f;
    float* f2s = (float*)f2s4;
    for (int t = tid; t < N; t += 1024) f2s[t] = g_f2[b*N + t];
    __syncthreads();

    int w = tid >> 5, lane = tid & 31;
    int row = b*N + i0 + w;
    float f1i = g_f1[row];
    const float4* __restrict__ arow = (const float4*)(adj + (size_t)row * N);
    float2* pbase = g_pairs + (size_t)row * MAXNNZ;
    unsigned lmask = (1u << lane) - 1u;
    int nnz = 0;

    int t = lane;
    float4 a0 = arow[t];
    float4 a1 = arow[t + 32];
#pragma unroll 1
    for (int it = 0; it < 16; it++) {
        float4 an;
        if (it < 14) an = arow[t + 64];

        unsigned msk = (a0.x != 0.f ? 1u : 0u) | (a0.y != 0.f ? 2u : 0u)
                     | (a0.z != 0.f ? 4u : 0u) | (a0.w != 0.f ? 8u : 0u);
        int c = __popc(msk);

        unsigned m0 = __ballot_sync(0xffffffffu, c & 1);
        unsigned m1 = __ballot_sync(0xffffffffu, c & 2);
        unsigned m2 = __ballot_sync(0xffffffffu, c & 4);
        int base = nnz + __popc(m0 & lmask) + 2*__popc(m1 & lmask) + 4*__popc(m2 & lmask);
        nnz += __popc(m0) + 2*__popc(m1) + 4*__popc(m2);

        if (msk) {
            float4 f2v = f2s4[t];
            do {
                int k = __ffs(msk) - 1;
                msk &= msk - 1;
                float fv = (k & 1) ? ((k & 2) ? f2v.w : f2v.y)
                                   : ((k & 2) ? f2v.z : f2v.x);
                float e = f1i + fv;
                e = (e >= 0.f) ? e : LRELU_SLOPE * e;
                float p = __expf(e) - 1.f;
                if (base < MAXNNZ)
                    pbase[base] = make_float2(__int_as_float(4*t + k), p);
                base++;
                atomicAdd(&Dpart[4*t + k], p);
            } while (msk);
        }
        a0 = a1; a1 = an; t += 32;
    }
    nnz = min(nnz, MAXNNZ);
    if (lane == 0) g_nnz[row] = nnz;
    int npad = (nnz + 7) & ~7;
    if (nnz + lane < npad) pbase[nnz + lane] = make_float2(0.f, 0.f);

    __syncthreads();
    for (int tt = tid; tt < N; tt += 1024) atomicAdd(&g_Dsum[b*N + tt], Dpart[tt]);
}

// ---------------- C: invD = 1/(N+Dsum); c[b,o] += sum_j invD[j]*h[j,o] ----------------
__global__ void k_cvec() {
    __shared__ float inv_s[64];
    __shared__ float part[512];
    int tid = threadIdx.x;
    int b  = blockIdx.x >> 5;
    int j0 = (blockIdx.x & 31) * 64;

    if (tid < 64) {
        float v = 1.f / ((float)N + g_Dsum[b*N + j0 + tid]);
        g_invD[b*N + j0 + tid] = v;
        inv_s[tid] = v;
    }
    __syncthreads();

    int r = tid >> 6, o = tid & 63;
    float acc = 0.f;
#pragma unroll
    for (int q = 0; q < 8; q++) {
        int jj = q*8 + r;
        acc += inv_s[jj] * g_h[(size_t)(b*N + j0 + jj)*F + o];
    }
    part[tid] = acc;
    __syncthreads();
    if (tid < 64) {
        float s = 0.f;
#pragma unroll
        for (int q = 0; q < 8; q++) s += part[q*64 + tid];
        atomicAdd(&g_c[b*F + tid], s);
    }
}

// ---------------- D: sparse fp16 gather, half-warp scheme (R9 proven) ----------------
__global__ void k_out(const float* __restrict__ in, const float* __restrict__ bias,
                      float* __restrict__ out) {
    __shared__ float  inv_s[N];                    // 8 KB
    __shared__ float2 pairs_s[16 * MAXNNZ];        // 32 KB (j*16 as int bits, w)
    int tid = threadIdx.x;
    int w = tid >> 5, lane = tid & 31;
    int half = lane >> 4, fl = lane & 15;
    int rowBase = blockIdx.x * 16;
    int b = rowBase >> 11;

    ((float4*)inv_s)[tid] = ((const float4*)(g_invD + b*N))[tid];
    __syncthreads();

    int row = rowBase + w;
    int i = row & (N - 1);
    int npad = (g_nnz[row] + 7) & ~7;
    {
        const float2* __restrict__ pbase = g_pairs + (size_t)row * MAXNNZ;
        float2* ps2 = pairs_s + w * MAXNNZ;
        for (int t = lane; t < npad; t += 32) {
            float2 pr = pbase[t];
            int j = __float_as_int(pr.x);
            ps2[t] = make_float2(__int_as_float(j * 16), pr.y * inv_s[j]);
        }
    }
    __syncwarp();

    const float2* __restrict__ ps2 = pairs_s + w * MAXNNZ;
    const uint2* __restrict__ hh = (const uint2*)(g_hh + (size_t)b*N*F);

    float ax = 0.f, ay = 0.f, az = 0.f, aw = 0.f;
#pragma unroll 1
    for (int k0 = 0; k0 < npad; k0 += 8) {
#pragma unroll
        for (int u = 0; u < 4; u++) {
            float2 pr = ps2[k0 + 2*u + half];
            int j16 = __float_as_int(pr.x);
            uint2 hv = hh[j16 + fl];
            float2 f01 = __half22float2(*(const __half2*)&hv.x);
            float2 f23 = __half22float2(*(const __half2*)&hv.y);
            ax += pr.y * f01.x;
            ay += pr.y * f01.y;
            az += pr.y * f23.x;
            aw += pr.y * f23.y;
        }
    }

    ax += __shfl_xor_sync(0xffffffffu, ax, 16);
    ay += __shfl_xor_sync(0xffffffffu, ay, 16);
    az += __shfl_xor_sync(0xffffffffu, az, 16);
    aw += __shfl_xor_sync(0xffffffffu, aw, 16);

    if (half == 0) {
        int off = row * F + fl * 4;
        float4 cv = ((const float4*)(g_c + b*F))[fl];
        float4 bv = ((const float4*)(bias + i*F))[fl];
        float4 iv = *(const float4*)(in + off);
        float v0 = ax + cv.x + bv.x + iv.x;
        float v1 = ay + cv.y + bv.y + iv.y;
        float v2 = az + cv.z + bv.z + iv.z;
        float v3 = aw + cv.w + bv.w + iv.w;
        float4 res;
        res.x = (v0 > 0.f) ? v0 : expm1f(v0);
        res.y = (v1 > 0.f) ? v1 : expm1f(v1);
        res.z = (v2 > 0.f) ? v2 : expm1f(v2);
        res.w = (v3 > 0.f) ? v3 : expm1f(v3);
        *(float4*)(out + off) = res;
    }
}

// ---------------- launch ----------------
extern "C" void kernel_launch(void* const* d_in, const int* in_sizes, int n_in,
                              void* d_out, int out_size) {
    const float* input = (const float*)d_in[0];
    const float* adj   = (const float*)d_in[1];
    const float* W     = (const float*)d_in[2];
    const float* a1    = (const float*)d_in[3];
    const float* a2    = (const float*)d_in[4];
    const float* bias  = (const float*)d_in[5];
    float* out = (float*)d_out;

    k_hproj<<<BN/8,  512>>>(input, W, a1, a2);
    k_scan <<<BN/32, 1024>>>(adj);
    k_cvec <<<B*32,  512>>>();
    k_out  <<<BN/16, 512>>>(input, bias, out);
}

// round 12
// speedup vs baseline: 1.2044x; 1.1799x over previous
#include <cuda_runtime.h>
#include <cuda_fp16.h>

#define B 8
#define N 2048
#define F 64
#define MAXNNZ 256
#define BN (B*N)  // 16384
#define LRELU_SLOPE 0.2f

// ---- scratch (static device arrays; re-initialized every launch) ----
__device__ float  g_h[BN*F];                       // 4 MB fp32 h (cvec path)
__device__ __half g_hh[BN*F];                      // 2 MB fp16 h (k_out gather path)
__device__ float  g_f1[BN];
__device__ float  g_f2[BN];
__device__ float  g_Dsum[BN];                      // sum of expm1 terms per column
__device__ float  g_invD[BN];
__device__ float  g_c[B*F];                        // per-batch constant row
__device__ int    g_nnz[BN];
__device__ float2 g_pairs[(size_t)BN*MAXNNZ];      // (j as int bits, p), zero-padded to %8

// ---------------- A: h = input@W (fp32 + fp16), f1/f2, zero accumulators ----------------
__global__ void k_hproj(const float* __restrict__ in, const float* __restrict__ W,
                        const float* __restrict__ a1, const float* __restrict__ a2) {
    __shared__ float Ws[F*F];
    __shared__ float a1s[F], a2s[F];
    __shared__ float ins[8*F];
    __shared__ float hs[8*F];
    int tid = threadIdx.x;
    int rowBase = blockIdx.x * 8;

    if (blockIdx.x < 32) g_Dsum[blockIdx.x * 512 + tid] = 0.f;
    if (blockIdx.x == 32 && tid < B*F) g_c[tid] = 0.f;

    for (int t = tid; t < F*F; t += 512) Ws[t] = W[t];
    if (tid < F) { a1s[tid] = a1[tid]; a2s[tid] = a2[tid]; }
    ins[tid] = in[rowBase*F + tid];
    __syncthreads();

    int r = tid >> 6, o = tid & 63;
    float acc = 0.f;
#pragma unroll
    for (int f = 0; f < F; f++) acc += ins[r*F + f] * Ws[f*F + o];
    g_h[(rowBase + r)*F + o]  = acc;
    g_hh[(rowBase + r)*F + o] = __float2half(acc);
    hs[tid] = acc;
    __syncthreads();

    int w = tid >> 5, lane = tid & 31;
    if (w < 8) {
        float v1 = hs[w*F + lane]*a1s[lane] + hs[w*F + lane + 32]*a1s[lane + 32];
        float v2 = hs[w*F + lane]*a2s[lane] + hs[w*F + lane + 32]*a2s[lane + 32];
#pragma unroll
        for (int off = 16; off; off >>= 1) {
            v1 += __shfl_down_sync(0xffffffffu, v1, off);
            v2 += __shfl_down_sync(0xffffffffu, v2, off);
        }
        if (lane == 0) { g_f1[rowBase + w] = v1; g_f2[rowBase + w] = v2; }
    }
}

// ---------------- B: two-phase scan — mask build (no ballots), 1 prefix, drain --------
// block = 512 threads = 16 warps = 16 rows; grid = BN/16.
__global__ void k_scan(const float* __restrict__ adj) {
    __shared__ float Dpart[N];        // 8 KB
    __shared__ float f2s[N];          // 8 KB
    int tid = threadIdx.x;
    int b  = blockIdx.x >> 7;
    int i0 = (blockIdx.x & 127) * 16;

    for (int t = tid; t < N; t += 512) Dpart[t] = 0.f;
    for (int t = tid; t < N; t += 512) f2s[t] = g_f2[b*N + t];
    __syncthreads();

    int w = tid >> 5, lane = tid & 31;
    int row = b*N + i0 + w;
    float f1i = g_f1[row];
    const float4* __restrict__ arow = (const float4*)(adj + (size_t)row * N);
    float2* pbase = g_pairs + (size_t)row * MAXNNZ;
    unsigned lmask = (1u << lane) - 1u;

    // ---- phase 1: stream adj, build per-lane 64-bit nonzero mask (no warp sync) ----
    unsigned long long m64 = 0ull;
    float4 a0 = arow[lane], a1 = arow[lane + 32];
#pragma unroll 1
    for (int it = 0; it < 16; it += 2) {
        float4 n0, n1;
        if (it < 14) {
            n0 = arow[(it + 2)*32 + lane];
            n1 = arow[(it + 3)*32 + lane];
        }
        unsigned mk0 = (a0.x != 0.f ? 1u : 0u) | (a0.y != 0.f ? 2u : 0u)
                     | (a0.z != 0.f ? 4u : 0u) | (a0.w != 0.f ? 8u : 0u);
        unsigned mk1 = (a1.x != 0.f ? 1u : 0u) | (a1.y != 0.f ? 2u : 0u)
                     | (a1.z != 0.f ? 4u : 0u) | (a1.w != 0.f ? 8u : 0u);
        m64 |= ((unsigned long long)(mk0 | (mk1 << 4))) << (4*it);
        a0 = n0; a1 = n1;
    }
    int cnt = __popcll(m64);

    // ---- one prefix across lanes (cnt <= 64 -> 7 count-bit ballots) ----
    int base = 0, total = 0;
#pragma unroll
    for (int bit = 0; bit < 7; bit++) {
        unsigned mm = __ballot_sync(0xffffffffu, (cnt >> bit) & 1);
        base  += __popc(mm & lmask) << bit;
        total += __popc(mm) << bit;
    }

    // ---- phase 2: drain set bits (independent per lane) ----
    while (m64) {
        int bitp = __ffsll(m64) - 1;
        m64 &= m64 - 1;
        int it = bitp >> 2, k = bitp & 3;
        int j = ((it*32 + lane) << 2) + k;
        float e = f1i + f2s[j];
        e = (e >= 0.f) ? e : LRELU_SLOPE * e;
        float p = __expf(e) - 1.f;
        if (base < MAXNNZ)
            pbase[base] = make_float2(__int_as_float(j), p);
        base++;
        atomicAdd(&Dpart[j], p);
    }

    int nnz = min(total, MAXNNZ);
    if (lane == 0) g_nnz[row] = nnz;
    int npad = (nnz + 7) & ~7;
    if (nnz + lane < npad) pbase[nnz + lane] = make_float2(0.f, 0.f);

    __syncthreads();
    for (int tt = tid; tt < N; tt += 512) atomicAdd(&g_Dsum[b*N + tt], Dpart[tt]);
}

// ---------------- C: invD = 1/(N+Dsum); c[b,o] += sum_j invD[j]*h[j,o] ----------------
__global__ void k_cvec() {
    __shared__ float inv_s[64];
    __shared__ float part[512];
    int tid = threadIdx.x;
    int b  = blockIdx.x >> 5;
    int j0 = (blockIdx.x & 31) * 64;

    if (tid < 64) {
        float v = 1.f / ((float)N + g_Dsum[b*N + j0 + tid]);
        g_invD[b*N + j0 + tid] = v;
        inv_s[tid] = v;
    }
    __syncthreads();

    int r = tid >> 6, o = tid & 63;
    float acc = 0.f;
#pragma unroll
    for (int q = 0; q < 8; q++) {
        int jj = q*8 + r;
        acc += inv_s[jj] * g_h[(size_t)(b*N + j0 + jj)*F + o];
    }
    part[tid] = acc;
    __syncthreads();
    if (tid < 64) {
        float s = 0.f;
#pragma unroll
        for (int q = 0; q < 8; q++) s += part[q*64 + tid];
        atomicAdd(&g_c[b*F + tid], s);
    }
}

// ---------------- D: sparse fp16 gather, half-warp scheme (R9 proven) ----------------
__global__ void k_out(const float* __restrict__ in, const float* __restrict__ bias,
                      float* __restrict__ out) {
    __shared__ float  inv_s[N];                    // 8 KB
    __shared__ float2 pairs_s[16 * MAXNNZ];        // 32 KB (j*16 as int bits, w)
    int tid = threadIdx.x;
    int w = tid >> 5, lane = tid & 31;
    int half = lane >> 4, fl = lane & 15;
    int rowBase = blockIdx.x * 16;
    int b = rowBase >> 11;

    ((float4*)inv_s)[tid] = ((const float4*)(g_invD + b*N))[tid];
    __syncthreads();

    int row = rowBase + w;
    int i = row & (N - 1);
    int npad = (g_nnz[row] + 7) & ~7;
    {
        const float2* __restrict__ pbase = g_pairs + (size_t)row * MAXNNZ;
        float2* ps2 = pairs_s + w * MAXNNZ;
        for (int t = lane; t < npad; t += 32) {
            float2 pr = pbase[t];
            int j = __float_as_int(pr.x);
            ps2[t] = make_float2(__int_as_float(j * 16), pr.y * inv_s[j]);
        }
    }
    __syncwarp();

    const float2* __restrict__ ps2 = pairs_s + w * MAXNNZ;
    const uint2* __restrict__ hh = (const uint2*)(g_hh + (size_t)b*N*F);

    float ax = 0.f, ay = 0.f, az = 0.f, aw = 0.f;
#pragma unroll 1
    for (int k0 = 0; k0 < npad; k0 += 8) {
#pragma unroll
        for (int u = 0; u < 4; u++) {
            float2 pr = ps2[k0 + 2*u + half];
            int j16 = __float_as_int(pr.x);
            uint2 hv = hh[j16 + fl];
            float2 f01 = __half22float2(*(const __half2*)&hv.x);
            float2 f23 = __half22float2(*(const __half2*)&hv.y);
            ax += pr.y * f01.x;
            ay += pr.y * f01.y;
            az += pr.y * f23.x;
            aw += pr.y * f23.y;
        }
    }

    ax += __shfl_xor_sync(0xffffffffu, ax, 16);
    ay += __shfl_xor_sync(0xffffffffu, ay, 16);
    az += __shfl_xor_sync(0xffffffffu, az, 16);
    aw += __shfl_xor_sync(0xffffffffu, aw, 16);

    if (half == 0) {
        int off = row * F + fl * 4;
        float4 cv = ((const float4*)(g_c + b*F))[fl];
        float4 bv = ((const float4*)(bias + i*F))[fl];
        float4 iv = *(const float4*)(in + off);
        float v0 = ax + cv.x + bv.x + iv.x;
        float v1 = ay + cv.y + bv.y + iv.y;
        float v2 = az + cv.z + bv.z + iv.z;
        float v3 = aw + cv.w + bv.w + iv.w;
        float4 res;
        res.x = (v0 > 0.f) ? v0 : expm1f(v0);
        res.y = (v1 > 0.f) ? v1 : expm1f(v1);
        res.z = (v2 > 0.f) ? v2 : expm1f(v2);
        res.w = (v3 > 0.f) ? v3 : expm1f(v3);
        *(float4*)(out + off) = res;
    }
}

// ---------------- launch ----------------
extern "C" void kernel_launch(void* const* d_in, const int* in_sizes, int n_in,
                              void* d_out, int out_size) {
    const float* input = (const float*)d_in[0];
    const float* adj   = (const float*)d_in[1];
    const float* W     = (const float*)d_in[2];
    const float* a1    = (const float*)d_in[3];
    const float* a2    = (const float*)d_in[4];
    const float* bias  = (const float*)d_in[5];
    float* out = (float*)d_out;

    k_hproj<<<BN/8,  512>>>(input, W, a1, a2);
    k_scan <<<BN/16, 512>>>(adj);
    k_cvec <<<B*32,  512>>>();
    k_out  <<<BN/16, 512>>>(input, bias, out);
}